// round 7
// baseline (speedup 1.0000x reference)
#include <cuda_runtime.h>
#include <cstdint>
#include <math.h>

#define NATOM 50000
#define MNBR  12
#define AFEA  64
#define BFEA  41
#define FAN   169
#define CO    128
#define NROW  600000
#define NT1   4688   // ceil(NROW/128) row tiles
#define NT0   391    // ceil(NATOM/128)
#define NBLK1 296    // k1 grid (148 CTAs per col-half)

// -------- scratch (device globals; allocation is forbidden) --------
__device__ float  g_PQ[NATOM * 256];             // [n][0:128]=P(self), [128:256]=Q(nbr)
__device__ float  g_gated[(size_t)NROW * CO];    // 307 MB pre-BN1 activations
__device__ float  g_sumed[NATOM * AFEA];
__device__ double g_p1s[NBLK1 * CO], g_p1q[NBLK1 * CO];
__device__ double g_p2s[NBLK1 * AFEA], g_p2q[NBLK1 * AFEA];
__device__ float  g_scale1[CO], g_shift1[CO], g_scale2[AFEA], g_shift2[AFEA];

// -------- packed f32x2 helpers (sm_103a) --------
typedef unsigned long long ull_t;
#define FMA2(d, a, b, c) asm("fma.rn.f32x2 %0, %1, %2, %3;" : "=l"(d) : "l"(a), "l"(b), "l"(c))
__device__ __forceinline__ void unpk(float& lo, float& hi, ull_t v) {
    unsigned a, b;
    asm("mov.b64 {%0, %1}, %2;" : "=r"(a), "=r"(b) : "l"(v));
    lo = __uint_as_float(a); hi = __uint_as_float(b);
}
__device__ __forceinline__ float sigm(float x) { return __fdividef(1.0f, 1.0f + __expf(-x)); }
__device__ __forceinline__ float splus(float x) {
    return fmaxf(x, 0.0f) + __logf(1.0f + __expf(-fabsf(x)));
}

// One k-step: 2 row-pairs x 8 cols. xrow: 4 consecutive rows (16B aligned);
// wrow: 8 duplicated weight pairs at 8B-aligned slots (conflict-free layout).
// 5 LDS + 16 FMA2, zero MOVs.
__device__ __forceinline__ void mma24(const float* __restrict__ xrow,
                                      const float* __restrict__ wrow,
                                      ull_t acc[2][8]) {
    ulonglong2 xv = *(const ulonglong2*)xrow;          // {r0,r1},{r2,r3}
    const ull_t* wp = (const ull_t*)wrow;              // 8 x {w,w}
#pragma unroll
    for (int c = 0; c < 8; ++c) {
        ull_t wd = wp[c];
        FMA2(acc[0][c], xv.x, wd, acc[0][c]);
        FMA2(acc[1][c], xv.y, wd, acc[1][c]);
    }
}

// wd layout: row stride 144 floats, col c in [0,64): slot (c>>3)*18 + (c&7)*2 (and +1 dup)
__device__ __forceinline__ int wslot(int c) { return (c >> 3) * 18 + (c & 7) * 2; }

// -------- k0: per-atom projections P,Q (grid: NT0 x 4 output tiles of 64) --------
__global__ __launch_bounds__(256, 2) void k0_proj(const float* __restrict__ atom,
                                                  const float* __restrict__ W) {
    __shared__ __align__(16) float xs[32 * 132];   // 16.9 KB
    __shared__ __align__(16) float wd[32 * 144];   // 18.4 KB (duplicated, padded)
    const int tid = threadIdx.x;
    const int tc = tid & 7, tr = tid >> 3;         // tc: 8 col-groups, tr: 32 row-groups
    const int r0 = blockIdx.x * 128;
    const int o0 = blockIdx.y * 64;                // global PQ output column base
    const int pq = o0 >> 7;                        // 0 = P (self), 1 = Q (nbr)
    const int wr0 = o0 & 127;                      // W row base
    const int kofs = pq * 64;                      // W col base

    ull_t acc[2][8];
#pragma unroll
    for (int p = 0; p < 2; ++p)
#pragma unroll
        for (int c = 0; c < 8; ++c) acc[p][c] = 0ULL;

    for (int kc = 0; kc < 2; ++kc) {
        __syncthreads();
        for (int i = tid; i < 128 * 32; i += 256) {
            int row = i >> 5, kk = i & 31;
            int gr = r0 + row;
            xs[kk * 132 + row] = (gr < NATOM) ? atom[gr * AFEA + kc * 32 + kk] : 0.0f;
        }
        for (int i = tid; i < 64 * 32; i += 256) {
            int c = i >> 5, kk = i & 31;
            float w = W[(wr0 + c) * FAN + kofs + kc * 32 + kk];
            int s = kk * 144 + wslot(c);
            wd[s] = w; wd[s + 1] = w;
        }
        __syncthreads();
#pragma unroll 4
        for (int kk = 0; kk < 32; ++kk)
            mma24(&xs[kk * 132 + tr * 4], &wd[kk * 144 + tc * 18], acc);
    }
#pragma unroll
    for (int p = 0; p < 2; ++p) {
        float vl[8], vh[8];
#pragma unroll
        for (int c = 0; c < 8; ++c) unpk(vl[c], vh[c], acc[p][c]);
        int r = tr * 4 + p * 2;
        int g0 = r0 + r, g1 = g0 + 1;
        if (g0 < NATOM) {
            float* dst = &g_PQ[(size_t)g0 * 256 + o0 + tc * 8];
            *(float4*)dst       = make_float4(vl[0], vl[1], vl[2], vl[3]);
            *(float4*)(dst + 4) = make_float4(vl[4], vl[5], vl[6], vl[7]);
        }
        if (g1 < NATOM) {
            float* dst = &g_PQ[(size_t)g1 * 256 + o0 + tc * 8];
            *(float4*)dst       = make_float4(vh[0], vh[1], vh[2], vh[3]);
            *(float4*)(dst + 4) = make_float4(vh[4], vh[5], vh[6], vh[7]);
        }
    }
}

// -------- k1: edge GEMM (128x64 tiles) + gather epilogue + BN1 partials --------
__global__ __launch_bounds__(256, 2) void k1_main(const float* __restrict__ nbr,
                                                  const int* __restrict__ idx,
                                                  const float* __restrict__ W,
                                                  const float* __restrict__ bvec) {
    __shared__ __align__(16) float xs[41 * 132];   // 21.6 KB
    __shared__ __align__(16) float wd[41 * 144];   // 23.6 KB
    __shared__ int sidx[128];
    __shared__ double red_s[64], red_q[64];
    const int tid = threadIdx.x;
    const int tc = tid & 7, tr = tid >> 3;
    const int ch = blockIdx.x & 1;                 // col half
    const int C0 = ch * 64;
    const int col0 = C0 + tc * 8;                  // global output channel base for this thread

    if (tid < 64) { red_s[tid] = 0.0; red_q[tid] = 0.0; }
    for (int i = tid; i < 64 * 41; i += 256) {     // edge weights (duplicated), loaded once
        int c = i / 41, kk = i - c * 41;
        float w = W[(C0 + c) * FAN + 128 + kk];
        int s = kk * 144 + wslot(c);
        wd[s] = w; wd[s + 1] = w;
    }
    float bv[8];
    {
        float4 b0 = *(const float4*)&bvec[col0];
        float4 b1 = *(const float4*)&bvec[col0 + 4];
        bv[0] = b0.x; bv[1] = b0.y; bv[2] = b0.z; bv[3] = b0.w;
        bv[4] = b1.x; bv[5] = b1.y; bv[6] = b1.z; bv[7] = b1.w;
    }
    float fs[8], fq[8];
#pragma unroll
    for (int c = 0; c < 8; ++c) { fs[c] = 0.0f; fq[c] = 0.0f; }

    for (int rt = blockIdx.x >> 1; rt < NT1; rt += 148) {
        const int r0 = rt * 128;
        __syncthreads();
        for (int i = tid; i < 128 * 41; i += 256) {
            int row = i / 41, kk = i - row * 41;
            long gi = (long)r0 * 41 + i;
            xs[kk * 132 + row] = (gi < (long)NROW * 41) ? nbr[gi] : 0.0f;
        }
        if (tid < 128) {
            int gr = r0 + tid;
            sidx[tid] = (gr < NROW) ? idx[gr] : 0;
        }
        __syncthreads();

        ull_t acc[2][8];
#pragma unroll
        for (int p = 0; p < 2; ++p)
#pragma unroll
            for (int c = 0; c < 8; ++c) acc[p][c] = 0ULL;
#pragma unroll 4
        for (int kk = 0; kk < 41; ++kk)
            mma24(&xs[kk * 132 + tr * 4], &wd[kk * 144 + tc * 18], acc);

#pragma unroll
        for (int p = 0; p < 2; ++p) {
            float va[2][8];
#pragma unroll
            for (int c = 0; c < 8; ++c) unpk(va[0][c], va[1][c], acc[p][c]);
#pragma unroll
            for (int e = 0; e < 2; ++e) {
                int lr = tr * 4 + p * 2 + e;
                int grow = r0 + lr;
                if (grow < NROW) {
                    float* v = va[e];
                    int n = grow / 12;
                    const float* Pp = &g_PQ[(size_t)n * 256 + col0];
                    float4 p0 = *(const float4*)Pp;
                    float4 p1 = *(const float4*)(Pp + 4);
                    const float* Qp = &g_PQ[(size_t)sidx[lr] * 256 + 128 + col0];
                    float4 q0 = *(const float4*)Qp;
                    float4 q1 = *(const float4*)(Qp + 4);
                    v[0] += p0.x + q0.x + bv[0]; v[1] += p0.y + q0.y + bv[1];
                    v[2] += p0.z + q0.z + bv[2]; v[3] += p0.w + q0.w + bv[3];
                    v[4] += p1.x + q1.x + bv[4]; v[5] += p1.y + q1.y + bv[5];
                    v[6] += p1.z + q1.z + bv[6]; v[7] += p1.w + q1.w + bv[7];
                    float* dst = &g_gated[(size_t)grow * 128 + col0];
                    *(float4*)dst       = make_float4(v[0], v[1], v[2], v[3]);
                    *(float4*)(dst + 4) = make_float4(v[4], v[5], v[6], v[7]);
#pragma unroll
                    for (int c = 0; c < 8; ++c) { fs[c] += v[c]; fq[c] += v[c] * v[c]; }
                }
            }
        }
    }
    __syncthreads();
#pragma unroll
    for (int c = 0; c < 8; ++c) {
        atomicAdd(&red_s[tc * 8 + c], (double)fs[c]);
        atomicAdd(&red_q[tc * 8 + c], (double)fq[c]);
    }
    __syncthreads();
    if (tid < 64) {
        g_p1s[blockIdx.x * CO + C0 + tid] = red_s[tid];
        g_p1q[blockIdx.x * CO + C0 + tid] = red_q[tid];
        g_p1s[blockIdx.x * CO + (C0 ^ 64) + tid] = 0.0;   // other half untouched by this CTA
        g_p1q[blockIdx.x * CO + (C0 ^ 64) + tid] = 0.0;
    }
}

// -------- k2: finalize BN1 (sum per-CTA partials) --------
__global__ void k2_fin(const float* __restrict__ g1, const float* __restrict__ b1) {
    int i = threadIdx.x;
    if (i < CO) {
        double s = 0.0, q = 0.0;
        for (int b = 0; b < NBLK1; ++b) { s += g_p1s[b * CO + i]; q += g_p1q[b * CO + i]; }
        double mean = s / (double)NROW;
        double var  = q / (double)NROW - mean * mean;
        float inv = (float)(1.0 / sqrt(var + 1e-5));
        float sc = g1[i] * inv;
        g_scale1[i] = sc;
        g_shift1[i] = b1[i] - (float)mean * sc;
    }
}

// -------- k3: BN1 affine + sigmoid*softplus + neighbor sum + BN2 partials --------
__global__ __launch_bounds__(256) void k3_reduce() {
    __shared__ float sc[128], sh[128];
    __shared__ double rs[64], rq[64];
    const int tid = threadIdx.x;
    if (tid < 128) { sc[tid] = g_scale1[tid]; sh[tid] = g_shift1[tid]; }
    if (tid < 64) { rs[tid] = 0.0; rq[tid] = 0.0; }
    __syncthreads();
    const int l = tid & 31;
    const int gw = (blockIdx.x * blockDim.x + tid) >> 5;
    const int nw = (gridDim.x * blockDim.x) >> 5;
    const float sf0 = sc[l],      hf0 = sh[l];
    const float sf1 = sc[l + 32], hf1 = sh[l + 32];
    const float sc0 = sc[l + 64], hc0 = sh[l + 64];
    const float sc1 = sc[l + 96], hc1 = sh[l + 96];
    float as0 = 0.f, aq0 = 0.f, as1 = 0.f, aq1 = 0.f;
    for (int n = gw; n < NATOM; n += nw) {
        float a0 = 0.f, a1 = 0.f;
        const float* g = &g_gated[(size_t)n * 12 * 128];
#pragma unroll 4
        for (int m = 0; m < 12; ++m) {
            float f0 = g[m * 128 + l]      * sf0 + hf0;
            float f1 = g[m * 128 + l + 32] * sf1 + hf1;
            float c0 = g[m * 128 + l + 64] * sc0 + hc0;
            float c1 = g[m * 128 + l + 96] * sc1 + hc1;
            a0 += sigm(f0) * splus(c0);
            a1 += sigm(f1) * splus(c1);
        }
        g_sumed[n * 64 + l]      = a0;
        g_sumed[n * 64 + l + 32] = a1;
        as0 += a0; aq0 += a0 * a0;
        as1 += a1; aq1 += a1 * a1;
    }
    atomicAdd(&rs[l], (double)as0);      atomicAdd(&rq[l], (double)aq0);
    atomicAdd(&rs[l + 32], (double)as1); atomicAdd(&rq[l + 32], (double)aq1);
    __syncthreads();
    if (tid < 64) {
        g_p2s[blockIdx.x * AFEA + tid] = rs[tid];
        g_p2q[blockIdx.x * AFEA + tid] = rq[tid];
    }
}

// -------- k4: finalize BN2 --------
__global__ void k4_fin(const float* __restrict__ g2, const float* __restrict__ b2) {
    int i = threadIdx.x;
    if (i < AFEA) {
        double s = 0.0, q = 0.0;
        for (int b = 0; b < NBLK1; ++b) { s += g_p2s[b * AFEA + i]; q += g_p2q[b * AFEA + i]; }
        double mean = s / (double)NATOM;
        double var  = q / (double)NATOM - mean * mean;
        float inv = (float)(1.0 / sqrt(var + 1e-5));
        float scv = g2[i] * inv;
        g_scale2[i] = scv;
        g_shift2[i] = b2[i] - (float)mean * scv;
    }
}

// -------- k5: final softplus --------
__global__ void k5_out(const float* __restrict__ atom, float* __restrict__ out) {
    int i = blockIdx.x * blockDim.x + threadIdx.x;
    if (i < NATOM * AFEA) {
        int a = i & 63;
        float v = atom[i] + g_sumed[i] * g_scale2[a] + g_shift2[a];
        out[i] = splus(v);
    }
}

extern "C" void kernel_launch(void* const* d_in, const int* in_sizes, int n_in,
                              void* d_out, int out_size) {
    const float* atom = (const float*)d_in[0];
    const float* nbr  = (const float*)d_in[1];
    const int*   idx  = (const int*)d_in[2];
    const float* W    = (const float*)d_in[3];
    const float* bvec = (const float*)d_in[4];
    const float* bn1g = (const float*)d_in[5];
    const float* bn1b = (const float*)d_in[6];
    const float* bn2g = (const float*)d_in[7];
    const float* bn2b = (const float*)d_in[8];
    float* out = (float*)d_out;
    (void)in_sizes; (void)n_in; (void)out_size;

    k0_proj<<<dim3(NT0, 4), 256>>>(atom, W);
    k1_main<<<NBLK1, 256>>>(nbr, idx, W, bvec);
    k2_fin<<<1, 128>>>(bn1g, bn1b);
    k3_reduce<<<NBLK1, 256>>>();
    k4_fin<<<1, 64>>>(bn2g, bn2b);
    k5_out<<<(NATOM * AFEA + 255) / 256, 256>>>(atom, out);
}